// round 15
// baseline (speedup 1.0000x reference)
#include <cuda_runtime.h>
#include <cuda_fp16.h>
#include <cstdint>
#include <math.h>

// Problem constants
#define S_LEN 8192
#define DMODEL 1024
#define NHEAD 16
#define DHEAD 64
#define NSEG 8
#define SEG 1024

// Scratch (device globals)
__device__ __half g_qk_h[S_LEN * 2 * DMODEL];        // [tok][ q | k ] roped fp16 (q in log2-domain scale)
__device__ __half g_vt[NSEG * NHEAD * DHEAD * SEG];  // [sg][h][d][tok] fp16
__device__ __half g_ah[S_LEN * DMODEL];              // hs fp16, then attn out fp16
__device__ __half g_wh[3 * DMODEL * DMODEL];
__device__ __half g_ph[DMODEL * DMODEL];

// ---------------------------------------------------------------------------
// helpers
// ---------------------------------------------------------------------------
__device__ __forceinline__ uint32_t smem_u32(const void* p) {
    uint32_t a;
    asm("{ .reg .u64 tmp; cvta.to.shared.u64 tmp, %1; cvt.u32.u64 %0, tmp; }"
        : "=r"(a) : "l"(p));
    return a;
}
__device__ __forceinline__ void cp16(uint32_t dst, const void* src) {
    asm volatile("cp.async.cg.shared.global [%0], [%1], 16;" :: "r"(dst), "l"(src));
}
#define CP_COMMIT() asm volatile("cp.async.commit_group;" ::: "memory")
#define CP_WAIT(n)  asm volatile("cp.async.wait_group %0;" :: "n"(n) : "memory")

#define LDSM_X4(r0, r1, r2, r3, addr)                                          \
    asm volatile("ldmatrix.sync.aligned.m8n8.x4.shared.b16 {%0,%1,%2,%3}, [%4];" \
        : "=r"(r0), "=r"(r1), "=r"(r2), "=r"(r3) : "r"(addr))

__device__ __forceinline__ void mma_f16(
    float c[4], unsigned a0, unsigned a1, unsigned a2, unsigned a3,
    unsigned b0, unsigned b1)
{
    asm volatile(
        "mma.sync.aligned.m16n8k16.row.col.f32.f16.f16.f32 "
        "{%0,%1,%2,%3},{%4,%5,%6,%7},{%8,%9},{%0,%1,%2,%3};"
        : "+f"(c[0]), "+f"(c[1]), "+f"(c[2]), "+f"(c[3])
        : "r"(a0), "r"(a1), "r"(a2), "r"(a3), "r"(b0), "r"(b1));
}
__device__ __forceinline__ unsigned pack_h2(float lo, float hi) {
    __half2 h = __floats2half2_rn(lo, hi);
    return *(unsigned*)&h;
}

// FMA-pipe 2^x (input already in log2 domain, x <= 0 after max-subtraction).
// Degree-4 poly on [-0.5, 0.5], magic-number rint, exponent-bit scaling.
// Rel err ~2e-5 (well below fp16 P rounding). Clamp at -125 -> ~0.
__device__ __forceinline__ float fexp2(float t) {
    t = fmaxf(t, -125.0f);
    float n = t + 12582912.0f;                    // 1.5*2^23 magic rint
    int   k = __float_as_int(n) - 0x4B400000;     // rint(t) as int
    float f = t - (n - 12582912.0f);              // frac in [-0.5, 0.5]
    float p = fmaf(f, 0.00967418f, 0.05550411f);
    p = fmaf(f, p, 0.24022651f);
    p = fmaf(f, p, 0.69314718f);
    p = fmaf(f, p, 1.0f);
    return __int_as_float(__float_as_int(p) + (k << 23));
}

// Convert fp32 -> fp16
__global__ void __launch_bounds__(256) conv_hi(
    const float* __restrict__ x, __half* __restrict__ hi, int n4)
{
    int i = blockIdx.x * 256 + threadIdx.x;
    if (i >= n4) return;
    float4 v = ((const float4*)x)[i];
    __half2* hp = (__half2*)(hi + 4 * (size_t)i);
    hp[0] = __floats2half2_rn(v.x, v.y);
    hp[1] = __floats2half2_rn(v.z, v.w);
}

// ---------------------------------------------------------------------------
// Shared GEMM config: BM=128, BN=128, BK=32; 8 warps (4m x 2n), warp 32x64.
// 3-stage cp.async, single sync/iter, 2 CTAs/SM.
// ---------------------------------------------------------------------------
#define GST 40
#define STG_H 10240
#define BOFF 5120
#define NSTAGE 3
#define GEMM_SMEM_B (NSTAGE * STG_H * 2)   // 61440 bytes

#define GEMM_PROLOGUE_COMMON()                                                 \
    extern __shared__ __half sg[];                                             \
    const uint32_t sbase = smem_u32(sg);                                       \
    const int t      = threadIdx.x;                                            \
    const int lane   = t & 31;                                                 \
    const int warp   = t >> 5;                                                 \
    const int warp_m = warp >> 1;                                              \
    const int warp_n = warp & 1;                                               \
    const int g      = lane >> 2;                                              \
    const int tg     = lane & 3;                                               \
    const int m0 = blockIdx.y * 128;                                           \
    const int n0 = blockIdx.x * 128;

#define LOAD_STAGE_Q(stg, k0)                                                  \
    {                                                                          \
        uint32_t bb = sbase + (stg) * (STG_H * 2);                             \
        _Pragma("unroll")                                                      \
        for (int i = 0; i < 2; i++) {                                          \
            int id = t + i * 256;                                              \
            int r = id >> 2, c = (id & 3) * 8;                                 \
            cp16(bb + (r * GST + c) * 2, Ah + (size_t)(m0 + r) * K + (k0) + c);\
            cp16(bb + (BOFF + r * GST + c) * 2,                                \
                 Bh + (size_t)(n0 + r) * K + (k0) + c);                        \
        }                                                                      \
        CP_COMMIT();                                                           \
    }

#define GEMM_MAINLOOP()                                                        \
    float accm[2][8][4];                                                       \
    _Pragma("unroll")                                                          \
    for (int mi = 0; mi < 2; mi++)                                             \
        _Pragma("unroll")                                                      \
        for (int nb = 0; nb < 8; nb++)                                         \
            _Pragma("unroll")                                                  \
            for (int i = 0; i < 4; i++) accm[mi][nb][i] = 0.0f;                \
    const int nch = K >> 5;                                                    \
    LOAD_STAGE_Q(0, 0);                                                        \
    LOAD_STAGE_Q(1, 32);                                                       \
    const int a_row = warp_m * 32 + (lane & 15);                               \
    const int a_hc  = (lane >> 4) * 8;                                         \
    const int b_row = warp_n * 64 + ((lane >> 4) << 3) + (lane & 7);           \
    const int b_hc  = ((lane >> 3) & 1) * 8;                                   \
    for (int it = 0; it < nch; it++) {                                         \
        CP_WAIT(1);                                                            \
        __syncthreads();                                                       \
        if (it + 2 < nch) {                                                    \
            LOAD_STAGE_Q((it + 2) % NSTAGE, (it + 2) * 32);                    \
        } else {                                                               \
            CP_COMMIT();                                                       \
        }                                                                      \
        uint32_t bb = sbase + (it % NSTAGE) * (STG_H * 2);                     \
        _Pragma("unroll")                                                      \
        for (int ks = 0; ks < 2; ks++) {                                       \
            unsigned ah[2][4], bh[4][4];                                       \
            _Pragma("unroll")                                                  \
            for (int mi = 0; mi < 2; mi++) {                                   \
                uint32_t a = bb + ((a_row + mi * 16) * GST + ks * 16 + a_hc) * 2; \
                LDSM_X4(ah[mi][0], ah[mi][1], ah[mi][2], ah[mi][3], a);        \
            }                                                                  \
            _Pragma("unroll")                                                  \
            for (int p = 0; p < 4; p++) {                                      \
                uint32_t b = bb + (BOFF + (b_row + p * 16) * GST + ks * 16 + b_hc) * 2; \
                LDSM_X4(bh[p][0], bh[p][1], bh[p][2], bh[p][3], b);            \
            }                                                                  \
            _Pragma("unroll")                                                  \
            for (int p = 0; p < 4; p++)                                        \
                _Pragma("unroll")                                              \
                for (int q = 0; q < 2; q++) {                                  \
                    int nb = 2 * p + q;                                        \
                    _Pragma("unroll")                                          \
                    for (int mi = 0; mi < 2; mi++)                             \
                        mma_f16(accm[mi][nb], ah[mi][0], ah[mi][1], ah[mi][2], \
                                ah[mi][3], bh[p][2 * q], bh[p][2 * q + 1]);    \
                }                                                              \
        }                                                                      \
    }

// ---------------------------------------------------------------------------
// QKV GEMM fused: epilogue applies bias + RoPE, writes fp16 q|k to g_qk_h
// (q scaled by 0.125*log2(e) -> scores come out in log2 domain);
// v transposed to g_vt.
// ---------------------------------------------------------------------------
__global__ void __launch_bounds__(256, 2) gemm_qkv_fused(
    const __half* __restrict__ Ah, const __half* __restrict__ Bh,
    const float* __restrict__ bias,
    const float* __restrict__ cosT, const float* __restrict__ sinT,
    __half* __restrict__ qk, __half* __restrict__ vt,
    int M, int N, int K)
{
    GEMM_PROLOGUE_COMMON();
    GEMM_MAINLOOP();

    const int sec = n0 >> 10;                          // 0=q, 1=k, 2=v
    const int col_in_sec = (n0 & 1023) + warp_n * 64;  // head*64

    if (sec < 2) {
        const float qs = (sec == 0) ? (0.125f * 1.44269504f) : 1.0f;
        const int outoff = sec * DMODEL + col_in_sec;
#pragma unroll
        for (int mi = 0; mi < 2; mi++) {
            int r0 = m0 + warp_m * 32 + mi * 16 + g;
#pragma unroll
            for (int nb = 0; nb < 4; nb++) {
                int d = nb * 8 + 2 * tg;
                int n_lo = n0 + warp_n * 64 + d;
                float bl0 = bias[n_lo],      bl1 = bias[n_lo + 1];
                float bh0 = bias[n_lo + 32], bh1 = bias[n_lo + 33];
#pragma unroll
                for (int hrow = 0; hrow < 2; hrow++) {
                    int row = r0 + hrow * 8;
                    float x0 = accm[mi][nb][2 * hrow + 0] + bl0;
                    float x1 = accm[mi][nb][2 * hrow + 1] + bl1;
                    float y0 = accm[mi][nb + 4][2 * hrow + 0] + bh0;
                    float y1 = accm[mi][nb + 4][2 * hrow + 1] + bh1;
                    float2 c1 = *(const float2*)&cosT[row * DHEAD + d];
                    float2 s1 = *(const float2*)&sinT[row * DHEAD + d];
                    float2 c2 = *(const float2*)&cosT[row * DHEAD + d + 32];
                    float2 s2 = *(const float2*)&sinT[row * DHEAD + d + 32];
                    __half2 lo = __floats2half2_rn((x0 * c1.x - y0 * s1.x) * qs,
                                                   (x1 * c1.y - y1 * s1.y) * qs);
                    __half2 hi = __floats2half2_rn((y0 * c2.x + x0 * s2.x) * qs,
                                                   (y1 * c2.y + x1 * s2.y) * qs);
                    __half* dst = qk + (size_t)row * (2 * DMODEL) + outoff + d;
                    *(__half2*)dst        = lo;
                    *(__half2*)(dst + 32) = hi;
                }
            }
        }
    } else {
        const int h  = col_in_sec >> 6;
        const int sgm = m0 >> 10;
        __half* vb = vt + ((size_t)(sgm * NHEAD + h) * DHEAD) * SEG;
#pragma unroll
        for (int mi = 0; mi < 2; mi++) {
            int r0 = m0 + warp_m * 32 + mi * 16 + g;
#pragma unroll
            for (int nb = 0; nb < 8; nb++) {
                int d = nb * 8 + 2 * tg;
                int n = n0 + warp_n * 64 + d;
                float b0 = bias[n], b1 = bias[n + 1];
#pragma unroll
                for (int hrow = 0; hrow < 2; hrow++) {
                    int row = r0 + hrow * 8;
                    int tin = row & 1023;
                    vb[(size_t)d * SEG + tin]       =
                        __float2half_rn(accm[mi][nb][2 * hrow + 0] + b0);
                    vb[(size_t)(d + 1) * SEG + tin] =
                        __float2half_rn(accm[mi][nb][2 * hrow + 1] + b1);
                }
            }
        }
    }
}

// ---------------------------------------------------------------------------
// Proj GEMM: plain fp16, 128x128 tiles, fp32 output + bias.
// ---------------------------------------------------------------------------
__global__ void __launch_bounds__(256, 2) gemm_f16_out(
    const __half* __restrict__ Ah, const __half* __restrict__ Bh,
    const float* __restrict__ bias, float* __restrict__ C,
    int M, int N, int K)
{
    GEMM_PROLOGUE_COMMON();
    GEMM_MAINLOOP();

#pragma unroll
    for (int mi = 0; mi < 2; mi++) {
        int row = m0 + warp_m * 32 + mi * 16 + g;
#pragma unroll
        for (int nb = 0; nb < 8; nb++) {
            int n = n0 + warp_n * 64 + nb * 8 + 2 * tg;
            float b0 = bias[n], b1 = bias[n + 1];
            float2 v;
            v.x = accm[mi][nb][0] + b0;
            v.y = accm[mi][nb][1] + b1;
            *(float2*)&C[(size_t)row * N + n] = v;
            v.x = accm[mi][nb][2] + b0;
            v.y = accm[mi][nb][3] + b1;
            *(float2*)&C[(size_t)(row + 8) * N + n] = v;
        }
    }
}

// ---------------------------------------------------------------------------
// fp16 tensor-core flash attention; scores in log2 domain, FMA-pipe 2^x.
// ---------------------------------------------------------------------------
#define HST 72
#define KTILE_H (64 * HST)

__global__ void __launch_bounds__(256, 2) attn_f16_kernel(
    const __half* __restrict__ qk, const __half* __restrict__ vt,
    __half* __restrict__ oh)
{
    __shared__ __half sm[4 * KTILE_H];
    __half* Qs = sm;

    const int mt = blockIdx.x;
    const int h  = blockIdx.y;
    const int sg = blockIdx.z;

    const int t    = threadIdx.x;
    const int lane = t & 31;
    const int warp = t >> 5;
    const int g    = lane >> 2;
    const int tg   = lane & 3;

    const int lm_row = lane & 7;
    const int lm_grp = lane >> 3;

    const __half* kbase = qk + DMODEL + h * DHEAD;
    const __half* vbase = vt + (size_t)(sg * NHEAD + h) * DHEAD * SEG;

#pragma unroll
    for (int i = 0; i < 4; i++) {
        int f  = t + i * 256;
        int r  = f >> 3;
        int c8 = (f & 7) * 8;
        int tok = sg * SEG + mt * 128 + r;
        uint4 v = *(const uint4*)(qk + (size_t)tok * (2 * DMODEL) + h * DHEAD + c8);
        *(uint4*)&Qs[r * HST + c8] = v;
    }
    __syncthreads();

    uint4 rk[2], rv[2];
    {
        const int r  = t >> 3;
        const int c8 = (t & 7) * 8;
        rk[0] = *(const uint4*)(kbase + (size_t)(sg * SEG + r) * (2 * DMODEL) + c8);
        rk[1] = *(const uint4*)(kbase + (size_t)(sg * SEG + r + 32) * (2 * DMODEL) + c8);
        rv[0] = *(const uint4*)(vbase + (size_t)r * SEG + c8);
        rv[1] = *(const uint4*)(vbase + (size_t)(r + 32) * SEG + c8);
    }

    unsigned qa[4][4];
    {
        int row = warp * 16 + g;
#pragma unroll
        for (int ks = 0; ks < 4; ks++) {
            int c = ks * 16 + 2 * tg;
            qa[ks][0] = *(const unsigned*)&Qs[row * HST + c];
            qa[ks][1] = *(const unsigned*)&Qs[(row + 8) * HST + c];
            qa[ks][2] = *(const unsigned*)&Qs[row * HST + c + 8];
            qa[ks][3] = *(const unsigned*)&Qs[(row + 8) * HST + c + 8];
        }
    }
    __syncthreads();

    {
        const int r  = t >> 3;
        const int c8 = (t & 7) * 8;
        *(uint4*)&sm[0 * KTILE_H + r * HST + c8]        = rk[0];
        *(uint4*)&sm[0 * KTILE_H + (r + 32) * HST + c8] = rk[1];
        *(uint4*)&sm[2 * KTILE_H + r * HST + c8]        = rv[0];
        *(uint4*)&sm[2 * KTILE_H + (r + 32) * HST + c8] = rv[1];
    }
    __syncthreads();

    float acc[8][4];
#pragma unroll
    for (int nb = 0; nb < 8; nb++)
#pragma unroll
        for (int i = 0; i < 4; i++) acc[nb][i] = 0.0f;
    float m_lo = -INFINITY, m_hi = -INFINITY, l_lo = 0.0f, l_hi = 0.0f;

    for (int jt = 0; jt < 16; jt++) {
        if (jt < 15) {
            const int r  = t >> 3;
            const int c8 = (t & 7) * 8;
            int j0n = (jt + 1) * 64;
            rk[0] = *(const uint4*)(kbase + (size_t)(sg * SEG + j0n + r) * (2 * DMODEL) + c8);
            rk[1] = *(const uint4*)(kbase + (size_t)(sg * SEG + j0n + r + 32) * (2 * DMODEL) + c8);
            rv[0] = *(const uint4*)(vbase + (size_t)r * SEG + j0n + c8);
            rv[1] = *(const uint4*)(vbase + (size_t)(r + 32) * SEG + j0n + c8);
        }

        const uint32_t kst = smem_u32(sm) + (jt & 1) * (KTILE_H * 2);
        const uint32_t vst = smem_u32(sm) + (2 + (jt & 1)) * (KTILE_H * 2);

        // ---- S = Q K^T (log2 domain) ----
        float sf[8][4];
#pragma unroll
        for (int nb = 0; nb < 8; nb++) {
            sf[nb][0] = sf[nb][1] = sf[nb][2] = sf[nb][3] = 0.0f;
            unsigned kb[8];
            uint32_t ka = kst + ((nb * 8 + lm_row) * HST + lm_grp * 8) * 2;
            LDSM_X4(kb[0], kb[1], kb[2], kb[3], ka);
            LDSM_X4(kb[4], kb[5], kb[6], kb[7], ka + 64);
#pragma unroll
            for (int ks = 0; ks < 4; ks++)
                mma_f16(sf[nb], qa[ks][0], qa[ks][1], qa[ks][2], qa[ks][3],
                        kb[2 * ks], kb[2 * ks + 1]);
        }

        // ---- online softmax (2^x on FMA pipe) ----
        float tmax_lo = -INFINITY, tmax_hi = -INFINITY;
#pragma unroll
        for (int nb = 0; nb < 8; nb++) {
            tmax_lo = fmaxf(tmax_lo, fmaxf(sf[nb][0], sf[nb][1]));
            tmax_hi = fmaxf(tmax_hi, fmaxf(sf[nb][2], sf[nb][3]));
        }
        tmax_lo = fmaxf(tmax_lo, __shfl_xor_sync(0xffffffffu, tmax_lo, 1));
        tmax_lo = fmaxf(tmax_lo, __shfl_xor_sync(0xffffffffu, tmax_lo, 2));
        tmax_hi = fmaxf(tmax_hi, __shfl_xor_sync(0xffffffffu, tmax_hi, 1));
        tmax_hi = fmaxf(tmax_hi, __shfl_xor_sync(0xffffffffu, tmax_hi, 2));

        float mn_lo = fmaxf(m_lo, tmax_lo);
        float mn_hi = fmaxf(m_hi, tmax_hi);
        float fac_lo = fexp2(m_lo - mn_lo);
        float fac_hi = fexp2(m_hi - mn_hi);
        m_lo = mn_lo; m_hi = mn_hi;

        float rs_lo = 0.0f, rs_hi = 0.0f;
#pragma unroll
        for (int nb = 0; nb < 8; nb++) {
            sf[nb][0] = fexp2(sf[nb][0] - m_lo);
            sf[nb][1] = fexp2(sf[nb][1] - m_lo);
            sf[nb][2] = fexp2(sf[nb][2] - m_hi);
            sf[nb][3] = fexp2(sf[nb][3] - m_hi);
            rs_lo += sf[nb][0] + sf[nb][1];
            rs_hi += sf[nb][2] + sf[nb][3];
        }
        rs_lo += __shfl_xor_sync(0xffffffffu, rs_lo, 1);
        rs_lo += __shfl_xor_sync(0xffffffffu, rs_lo, 2);
        rs_hi += __shfl_xor_sync(0xffffffffu, rs_hi, 1);
        rs_hi += __shfl_xor_sync(0xffffffffu, rs_hi, 2);

        l_lo = l_lo * fac_lo + rs_lo;
        l_hi = l_hi * fac_hi + rs_hi;
#pragma unroll
        for (int nb = 0; nb < 8; nb++) {
            acc[nb][0] *= fac_lo; acc[nb][1] *= fac_lo;
            acc[nb][2] *= fac_hi; acc[nb][3] *= fac_hi;
        }

        // ---- acc += P V ----
        unsigned pa[4][4];
#pragma unroll
        for (int kc = 0; kc < 4; kc++) {
            pa[kc][0] = pack_h2(sf[2 * kc][0],     sf[2 * kc][1]);
            pa[kc][1] = pack_h2(sf[2 * kc][2],     sf[2 * kc][3]);
            pa[kc][2] = pack_h2(sf[2 * kc + 1][0], sf[2 * kc + 1][1]);
            pa[kc][3] = pack_h2(sf[2 * kc + 1][2], sf[2 * kc + 1][3]);
        }
#pragma unroll
        for (int nb = 0; nb < 8; nb++) {
            unsigned vv[8];
            uint32_t va = vst + ((nb * 8 + lm_row) * HST + lm_grp * 8) * 2;
            LDSM_X4(vv[0], vv[1], vv[2], vv[3], va);
            LDSM_X4(vv[4], vv[5], vv[6], vv[7], va + 64);
#pragma unroll
            for (int kc = 0; kc < 4; kc++)
                mma_f16(acc[nb], pa[kc][0], pa[kc][1], pa[kc][2], pa[kc][3],
                        vv[2 * kc], vv[2 * kc + 1]);
        }

        if (jt < 15) {
            __half* Kd = sm + ((jt + 1) & 1) * KTILE_H;
            __half* Vd = sm + 2 * KTILE_H + ((jt + 1) & 1) * KTILE_H;
            const int r  = t >> 3;
            const int c8 = (t & 7) * 8;
            *(uint4*)&Kd[r * HST + c8]        = rk[0];
            *(uint4*)&Kd[(r + 32) * HST + c8] = rk[1];
            *(uint4*)&Vd[r * HST + c8]        = rv[0];
            *(uint4*)&Vd[(r + 32) * HST + c8] = rv[1];
        }
        __syncthreads();
    }

    float inv_lo = 1.0f / l_lo;
    float inv_hi = 1.0f / l_hi;
    int tok_lo = sg * SEG + mt * 128 + warp * 16 + g;
#pragma unroll
    for (int nb = 0; nb < 8; nb++) {
        int col = h * DHEAD + nb * 8 + tg * 2;
        *(__half2*)&oh[(size_t)tok_lo * DMODEL + col] =
            __floats2half2_rn(acc[nb][0] * inv_lo, acc[nb][1] * inv_lo);
        *(__half2*)&oh[(size_t)(tok_lo + 8) * DMODEL + col] =
            __floats2half2_rn(acc[nb][2] * inv_hi, acc[nb][3] * inv_hi);
    }
}

// ---------------------------------------------------------------------------
// Launch
// ---------------------------------------------------------------------------
extern "C" void kernel_launch(void* const* d_in, const int* in_sizes, int n_in,
                              void* d_out, int out_size)
{
    const float* hs     = (const float*)d_in[0];
    const float* cosT   = (const float*)d_in[1];
    const float* sinT   = (const float*)d_in[2];
    const float* qkv_w  = (const float*)d_in[3];
    const float* qkv_b  = (const float*)d_in[4];
    const float* proj_w = (const float*)d_in[5];
    const float* proj_b = (const float*)d_in[6];
    float* out = (float*)d_out;

    void *qkh_v, *vt_v, *ah_v, *wh_v, *ph_v;
    cudaGetSymbolAddress(&qkh_v, g_qk_h);
    cudaGetSymbolAddress(&vt_v, g_vt);
    cudaGetSymbolAddress(&ah_v, g_ah);
    cudaGetSymbolAddress(&wh_v, g_wh);
    cudaGetSymbolAddress(&ph_v, g_ph);
    __half* qkh  = (__half*)qkh_v;
    __half* vtp  = (__half*)vt_v;
    __half* ahp  = (__half*)ah_v;
    __half* whp  = (__half*)wh_v;
    __half* php  = (__half*)ph_v;

    cudaFuncSetAttribute(gemm_qkv_fused,
                         cudaFuncAttributeMaxDynamicSharedMemorySize, GEMM_SMEM_B);
    cudaFuncSetAttribute(gemm_f16_out,
                         cudaFuncAttributeMaxDynamicSharedMemorySize, GEMM_SMEM_B);

    // 0) Converts
    conv_hi<<<(S_LEN * DMODEL / 4) / 256, 256>>>(hs, ahp, S_LEN * DMODEL / 4);
    conv_hi<<<(3 * DMODEL * DMODEL / 4) / 256, 256>>>(qkv_w, whp, 3 * DMODEL * DMODEL / 4);
    conv_hi<<<(DMODEL * DMODEL / 4) / 256, 256>>>(proj_w, php, DMODEL * DMODEL / 4);

    // 1) QKV GEMM with fused bias+RoPE+fp16 epilogue -> g_qk_h / g_vt
    {
        dim3 grid(3 * DMODEL / 128, S_LEN / 128);
        gemm_qkv_fused<<<grid, 256, GEMM_SMEM_B>>>(
            ahp, whp, qkv_b, cosT, sinT, qkh, vtp, S_LEN, 3 * DMODEL, DMODEL);
    }

    // 2) Attention -> fp16 proj input (g_ah reused)
    {
        dim3 grid(SEG / 128, NHEAD, NSEG);
        attn_f16_kernel<<<grid, 256>>>(qkh, vtp, ahp);
    }

    // 3) Output projection (plain fp16, 128x128 tiles)
    {
        dim3 grid(DMODEL / 128, S_LEN / 128);
        gemm_f16_out<<<grid, 256, GEMM_SMEM_B>>>(
            ahp, php, proj_b, out, S_LEN, DMODEL, DMODEL);
    }
}

// round 16
// speedup vs baseline: 1.1094x; 1.1094x over previous
#include <cuda_runtime.h>
#include <cuda_fp16.h>
#include <cstdint>
#include <math.h>

// Problem constants
#define S_LEN 8192
#define DMODEL 1024
#define NHEAD 16
#define DHEAD 64
#define NSEG 8
#define SEG 1024

// Scratch (device globals)
__device__ __half g_qk_h[S_LEN * 2 * DMODEL];        // [tok][ q | k ] roped fp16 (q log2-scaled)
__device__ __half g_vt[NSEG * NHEAD * DHEAD * SEG];  // [sg][h][d][tok] fp16
__device__ __half g_ah[S_LEN * DMODEL];              // hs fp16, then attn out fp16
__device__ __half g_wh[3 * DMODEL * DMODEL];
__device__ __half g_ph[DMODEL * DMODEL];

// ---------------------------------------------------------------------------
// helpers
// ---------------------------------------------------------------------------
__device__ __forceinline__ uint32_t smem_u32(const void* p) {
    uint32_t a;
    asm("{ .reg .u64 tmp; cvta.to.shared.u64 tmp, %1; cvt.u32.u64 %0, tmp; }"
        : "=r"(a) : "l"(p));
    return a;
}
__device__ __forceinline__ void cp16(uint32_t dst, const void* src) {
    asm volatile("cp.async.cg.shared.global [%0], [%1], 16;" :: "r"(dst), "l"(src));
}
#define CP_COMMIT() asm volatile("cp.async.commit_group;" ::: "memory")
#define CP_WAIT(n)  asm volatile("cp.async.wait_group %0;" :: "n"(n) : "memory")

#define LDSM_X4(r0, r1, r2, r3, addr)                                          \
    asm volatile("ldmatrix.sync.aligned.m8n8.x4.shared.b16 {%0,%1,%2,%3}, [%4];" \
        : "=r"(r0), "=r"(r1), "=r"(r2), "=r"(r3) : "r"(addr))

__device__ __forceinline__ void mma_f16(
    float c[4], unsigned a0, unsigned a1, unsigned a2, unsigned a3,
    unsigned b0, unsigned b1)
{
    asm volatile(
        "mma.sync.aligned.m16n8k16.row.col.f32.f16.f16.f32 "
        "{%0,%1,%2,%3},{%4,%5,%6,%7},{%8,%9},{%0,%1,%2,%3};"
        : "+f"(c[0]), "+f"(c[1]), "+f"(c[2]), "+f"(c[3])
        : "r"(a0), "r"(a1), "r"(a2), "r"(a3), "r"(b0), "r"(b1));
}
__device__ __forceinline__ unsigned pack_h2(float lo, float hi) {
    __half2 h = __floats2half2_rn(lo, hi);
    return *(unsigned*)&h;
}
// single-MUFU 2^x (input in log2 domain)
__device__ __forceinline__ float ex2(float x) {
    float r;
    asm("ex2.approx.f32 %0, %1;" : "=f"(r) : "f"(x));
    return r;
}

// Convert fp32 -> fp16
__global__ void __launch_bounds__(256) conv_hi(
    const float* __restrict__ x, __half* __restrict__ hi, int n4)
{
    int i = blockIdx.x * 256 + threadIdx.x;
    if (i >= n4) return;
    float4 v = ((const float4*)x)[i];
    __half2* hp = (__half2*)(hi + 4 * (size_t)i);
    hp[0] = __floats2half2_rn(v.x, v.y);
    hp[1] = __floats2half2_rn(v.z, v.w);
}

// ---------------------------------------------------------------------------
// GEMM config: BM=128, BN=128, BK=64; 8 warps (4m x 2n), warp 32x64.
// 3-stage cp.async, single sync/iter, 2 CTAs/SM (221 KB smem total).
// stage (halves, stride 72): A[128x64] @0 | B[128x64] @9216. 36864 B/stage.
// ---------------------------------------------------------------------------
#define GST 72
#define STG_H 18432
#define BOFF 9216
#define NSTAGE 3
#define GEMM_SMEM_B (NSTAGE * STG_H * 2)   // 110592 bytes

#define GEMM_PROLOGUE_COMMON()                                                 \
    extern __shared__ __half sg[];                                             \
    const uint32_t sbase = smem_u32(sg);                                       \
    const int t      = threadIdx.x;                                            \
    const int lane   = t & 31;                                                 \
    const int warp   = t >> 5;                                                 \
    const int warp_m = warp >> 1;                                              \
    const int warp_n = warp & 1;                                               \
    const int g      = lane >> 2;                                              \
    const int tg     = lane & 3;                                               \
    const int m0 = blockIdx.y * 128;                                           \
    const int n0 = blockIdx.x * 128;

#define LOAD_STAGE_Q(stg, k0)                                                  \
    {                                                                          \
        uint32_t bb = sbase + (stg) * (STG_H * 2);                             \
        _Pragma("unroll")                                                      \
        for (int i = 0; i < 4; i++) {                                          \
            int id = t + i * 256;                                              \
            int r = id >> 3, c = (id & 7) * 8;                                 \
            cp16(bb + (r * GST + c) * 2, Ah + (size_t)(m0 + r) * K + (k0) + c);\
            cp16(bb + (BOFF + r * GST + c) * 2,                                \
                 Bh + (size_t)(n0 + r) * K + (k0) + c);                        \
        }                                                                      \
        CP_COMMIT();                                                           \
    }

#define GEMM_MAINLOOP()                                                        \
    float accm[2][8][4];                                                       \
    _Pragma("unroll")                                                          \
    for (int mi = 0; mi < 2; mi++)                                             \
        _Pragma("unroll")                                                      \
        for (int nb = 0; nb < 8; nb++)                                         \
            _Pragma("unroll")                                                  \
            for (int i = 0; i < 4; i++) accm[mi][nb][i] = 0.0f;                \
    const int nch = K >> 6;                                                    \
    LOAD_STAGE_Q(0, 0);                                                        \
    LOAD_STAGE_Q(1, 64);                                                       \
    const int a_row = warp_m * 32 + (lane & 15);                               \
    const int a_hc  = (lane >> 4) * 8;                                         \
    const int b_row = warp_n * 64 + ((lane >> 4) << 3) + (lane & 7);           \
    const int b_hc  = ((lane >> 3) & 1) * 8;                                   \
    for (int it = 0; it < nch; it++) {                                         \
        CP_WAIT(1);                                                            \
        __syncthreads();                                                       \
        if (it + 2 < nch) {                                                    \
            LOAD_STAGE_Q((it + 2) % NSTAGE, (it + 2) * 64);                    \
        } else {                                                               \
            CP_COMMIT();                                                       \
        }                                                                      \
        uint32_t bb = sbase + (it % NSTAGE) * (STG_H * 2);                     \
        _Pragma("unroll")                                                      \
        for (int ks = 0; ks < 4; ks++) {                                       \
            unsigned ah[2][4], bh[4][4];                                       \
            _Pragma("unroll")                                                  \
            for (int mi = 0; mi < 2; mi++) {                                   \
                uint32_t a = bb + ((a_row + mi * 16) * GST + ks * 16 + a_hc) * 2; \
                LDSM_X4(ah[mi][0], ah[mi][1], ah[mi][2], ah[mi][3], a);        \
            }                                                                  \
            _Pragma("unroll")                                                  \
            for (int p = 0; p < 4; p++) {                                      \
                uint32_t b = bb + (BOFF + (b_row + p * 16) * GST + ks * 16 + b_hc) * 2; \
                LDSM_X4(bh[p][0], bh[p][1], bh[p][2], bh[p][3], b);            \
            }                                                                  \
            _Pragma("unroll")                                                  \
            for (int p = 0; p < 4; p++)                                        \
                _Pragma("unroll")                                              \
                for (int q = 0; q < 2; q++) {                                  \
                    int nb = 2 * p + q;                                        \
                    _Pragma("unroll")                                          \
                    for (int mi = 0; mi < 2; mi++)                             \
                        mma_f16(accm[mi][nb], ah[mi][0], ah[mi][1], ah[mi][2], \
                                ah[mi][3], bh[p][2 * q], bh[p][2 * q + 1]);    \
                }                                                              \
        }                                                                      \
    }

// ---------------------------------------------------------------------------
// QKV GEMM fused: epilogue applies bias + RoPE, writes fp16 q|k to g_qk_h
// (q scaled by 0.125*log2(e)); v transposed to g_vt.
// ---------------------------------------------------------------------------
__global__ void __launch_bounds__(256, 2) gemm_qkv_fused(
    const __half* __restrict__ Ah, const __half* __restrict__ Bh,
    const float* __restrict__ bias,
    const float* __restrict__ cosT, const float* __restrict__ sinT,
    __half* __restrict__ qk, __half* __restrict__ vt,
    int M, int N, int K)
{
    GEMM_PROLOGUE_COMMON();
    GEMM_MAINLOOP();

    const int sec = n0 >> 10;                          // 0=q, 1=k, 2=v
    const int col_in_sec = (n0 & 1023) + warp_n * 64;  // head*64

    if (sec < 2) {
        const float qs = (sec == 0) ? (0.125f * 1.44269504f) : 1.0f;
        const int outoff = sec * DMODEL + col_in_sec;
#pragma unroll
        for (int mi = 0; mi < 2; mi++) {
            int r0 = m0 + warp_m * 32 + mi * 16 + g;
#pragma unroll
            for (int nb = 0; nb < 4; nb++) {
                int d = nb * 8 + 2 * tg;
                int n_lo = n0 + warp_n * 64 + d;
                float bl0 = bias[n_lo],      bl1 = bias[n_lo + 1];
                float bh0 = bias[n_lo + 32], bh1 = bias[n_lo + 33];
#pragma unroll
                for (int hrow = 0; hrow < 2; hrow++) {
                    int row = r0 + hrow * 8;
                    float x0 = accm[mi][nb][2 * hrow + 0] + bl0;
                    float x1 = accm[mi][nb][2 * hrow + 1] + bl1;
                    float y0 = accm[mi][nb + 4][2 * hrow + 0] + bh0;
                    float y1 = accm[mi][nb + 4][2 * hrow + 1] + bh1;
                    float2 c1 = *(const float2*)&cosT[row * DHEAD + d];
                    float2 s1 = *(const float2*)&sinT[row * DHEAD + d];
                    float2 c2 = *(const float2*)&cosT[row * DHEAD + d + 32];
                    float2 s2 = *(const float2*)&sinT[row * DHEAD + d + 32];
                    __half2 lo = __floats2half2_rn((x0 * c1.x - y0 * s1.x) * qs,
                                                   (x1 * c1.y - y1 * s1.y) * qs);
                    __half2 hi = __floats2half2_rn((y0 * c2.x + x0 * s2.x) * qs,
                                                   (y1 * c2.y + x1 * s2.y) * qs);
                    __half* dst = qk + (size_t)row * (2 * DMODEL) + outoff + d;
                    *(__half2*)dst        = lo;
                    *(__half2*)(dst + 32) = hi;
                }
            }
        }
    } else {
        const int h  = col_in_sec >> 6;
        const int sgm = m0 >> 10;
        __half* vb = vt + ((size_t)(sgm * NHEAD + h) * DHEAD) * SEG;
#pragma unroll
        for (int mi = 0; mi < 2; mi++) {
            int r0 = m0 + warp_m * 32 + mi * 16 + g;
#pragma unroll
            for (int nb = 0; nb < 8; nb++) {
                int d = nb * 8 + 2 * tg;
                int n = n0 + warp_n * 64 + d;
                float b0 = bias[n], b1 = bias[n + 1];
#pragma unroll
                for (int hrow = 0; hrow < 2; hrow++) {
                    int row = r0 + hrow * 8;
                    int tin = row & 1023;
                    vb[(size_t)d * SEG + tin]       =
                        __float2half_rn(accm[mi][nb][2 * hrow + 0] + b0);
                    vb[(size_t)(d + 1) * SEG + tin] =
                        __float2half_rn(accm[mi][nb][2 * hrow + 1] + b1);
                }
            }
        }
    }
}

// ---------------------------------------------------------------------------
// Proj GEMM: plain fp16, 128x128 tiles, fp32 output + bias.
// ---------------------------------------------------------------------------
__global__ void __launch_bounds__(256, 2) gemm_f16_out(
    const __half* __restrict__ Ah, const __half* __restrict__ Bh,
    const float* __restrict__ bias, float* __restrict__ C,
    int M, int N, int K)
{
    GEMM_PROLOGUE_COMMON();
    GEMM_MAINLOOP();

#pragma unroll
    for (int mi = 0; mi < 2; mi++) {
        int row = m0 + warp_m * 32 + mi * 16 + g;
#pragma unroll
        for (int nb = 0; nb < 8; nb++) {
            int n = n0 + warp_n * 64 + nb * 8 + 2 * tg;
            float b0 = bias[n], b1 = bias[n + 1];
            float2 v;
            v.x = accm[mi][nb][0] + b0;
            v.y = accm[mi][nb][1] + b1;
            *(float2*)&C[(size_t)row * N + n] = v;
            v.x = accm[mi][nb][2] + b0;
            v.y = accm[mi][nb][3] + b1;
            *(float2*)&C[(size_t)(row + 8) * N + n] = v;
        }
    }
}

// ---------------------------------------------------------------------------
// fp16 tensor-core flash attention; scores in log2 domain, single-MUFU ex2.
// ---------------------------------------------------------------------------
#define HST 72
#define KTILE_H (64 * HST)

__global__ void __launch_bounds__(256, 2) attn_f16_kernel(
    const __half* __restrict__ qk, const __half* __restrict__ vt,
    __half* __restrict__ oh)
{
    __shared__ __half sm[4 * KTILE_H];
    __half* Qs = sm;

    const int mt = blockIdx.x;
    const int h  = blockIdx.y;
    const int sg = blockIdx.z;

    const int t    = threadIdx.x;
    const int lane = t & 31;
    const int warp = t >> 5;
    const int g    = lane >> 2;
    const int tg   = lane & 3;

    const int lm_row = lane & 7;
    const int lm_grp = lane >> 3;

    const __half* kbase = qk + DMODEL + h * DHEAD;
    const __half* vbase = vt + (size_t)(sg * NHEAD + h) * DHEAD * SEG;

#pragma unroll
    for (int i = 0; i < 4; i++) {
        int f  = t + i * 256;
        int r  = f >> 3;
        int c8 = (f & 7) * 8;
        int tok = sg * SEG + mt * 128 + r;
        uint4 v = *(const uint4*)(qk + (size_t)tok * (2 * DMODEL) + h * DHEAD + c8);
        *(uint4*)&Qs[r * HST + c8] = v;
    }
    __syncthreads();

    uint4 rk[2], rv[2];
    {
        const int r  = t >> 3;
        const int c8 = (t & 7) * 8;
        rk[0] = *(const uint4*)(kbase + (size_t)(sg * SEG + r) * (2 * DMODEL) + c8);
        rk[1] = *(const uint4*)(kbase + (size_t)(sg * SEG + r + 32) * (2 * DMODEL) + c8);
        rv[0] = *(const uint4*)(vbase + (size_t)r * SEG + c8);
        rv[1] = *(const uint4*)(vbase + (size_t)(r + 32) * SEG + c8);
    }

    unsigned qa[4][4];
    {
        int row = warp * 16 + g;
#pragma unroll
        for (int ks = 0; ks < 4; ks++) {
            int c = ks * 16 + 2 * tg;
            qa[ks][0] = *(const unsigned*)&Qs[row * HST + c];
            qa[ks][1] = *(const unsigned*)&Qs[(row + 8) * HST + c];
            qa[ks][2] = *(const unsigned*)&Qs[row * HST + c + 8];
            qa[ks][3] = *(const unsigned*)&Qs[(row + 8) * HST + c + 8];
        }
    }
    __syncthreads();

    {
        const int r  = t >> 3;
        const int c8 = (t & 7) * 8;
        *(uint4*)&sm[0 * KTILE_H + r * HST + c8]        = rk[0];
        *(uint4*)&sm[0 * KTILE_H + (r + 32) * HST + c8] = rk[1];
        *(uint4*)&sm[2 * KTILE_H + r * HST + c8]        = rv[0];
        *(uint4*)&sm[2 * KTILE_H + (r + 32) * HST + c8] = rv[1];
    }
    __syncthreads();

    float acc[8][4];
#pragma unroll
    for (int nb = 0; nb < 8; nb++)
#pragma unroll
        for (int i = 0; i < 4; i++) acc[nb][i] = 0.0f;
    float m_lo = -INFINITY, m_hi = -INFINITY, l_lo = 0.0f, l_hi = 0.0f;

    for (int jt = 0; jt < 16; jt++) {
        if (jt < 15) {
            const int r  = t >> 3;
            const int c8 = (t & 7) * 8;
            int j0n = (jt + 1) * 64;
            rk[0] = *(const uint4*)(kbase + (size_t)(sg * SEG + j0n + r) * (2 * DMODEL) + c8);
            rk[1] = *(const uint4*)(kbase + (size_t)(sg * SEG + j0n + r + 32) * (2 * DMODEL) + c8);
            rv[0] = *(const uint4*)(vbase + (size_t)r * SEG + j0n + c8);
            rv[1] = *(const uint4*)(vbase + (size_t)(r + 32) * SEG + j0n + c8);
        }

        const uint32_t kst = smem_u32(sm) + (jt & 1) * (KTILE_H * 2);
        const uint32_t vst = smem_u32(sm) + (2 + (jt & 1)) * (KTILE_H * 2);

        // ---- S = Q K^T (log2 domain) ----
        float sf[8][4];
#pragma unroll
        for (int nb = 0; nb < 8; nb++) {
            sf[nb][0] = sf[nb][1] = sf[nb][2] = sf[nb][3] = 0.0f;
            unsigned kb[8];
            uint32_t ka = kst + ((nb * 8 + lm_row) * HST + lm_grp * 8) * 2;
            LDSM_X4(kb[0], kb[1], kb[2], kb[3], ka);
            LDSM_X4(kb[4], kb[5], kb[6], kb[7], ka + 64);
#pragma unroll
            for (int ks = 0; ks < 4; ks++)
                mma_f16(sf[nb], qa[ks][0], qa[ks][1], qa[ks][2], qa[ks][3],
                        kb[2 * ks], kb[2 * ks + 1]);
        }

        // ---- online softmax (2^x, one MUFU op each) ----
        float tmax_lo = -INFINITY, tmax_hi = -INFINITY;
#pragma unroll
        for (int nb = 0; nb < 8; nb++) {
            tmax_lo = fmaxf(tmax_lo, fmaxf(sf[nb][0], sf[nb][1]));
            tmax_hi = fmaxf(tmax_hi, fmaxf(sf[nb][2], sf[nb][3]));
        }
        tmax_lo = fmaxf(tmax_lo, __shfl_xor_sync(0xffffffffu, tmax_lo, 1));
        tmax_lo = fmaxf(tmax_lo, __shfl_xor_sync(0xffffffffu, tmax_lo, 2));
        tmax_hi = fmaxf(tmax_hi, __shfl_xor_sync(0xffffffffu, tmax_hi, 1));
        tmax_hi = fmaxf(tmax_hi, __shfl_xor_sync(0xffffffffu, tmax_hi, 2));

        float mn_lo = fmaxf(m_lo, tmax_lo);
        float mn_hi = fmaxf(m_hi, tmax_hi);
        float fac_lo = ex2(m_lo - mn_lo);
        float fac_hi = ex2(m_hi - mn_hi);
        m_lo = mn_lo; m_hi = mn_hi;

        float rs_lo = 0.0f, rs_hi = 0.0f;
#pragma unroll
        for (int nb = 0; nb < 8; nb++) {
            sf[nb][0] = ex2(sf[nb][0] - m_lo);
            sf[nb][1] = ex2(sf[nb][1] - m_lo);
            sf[nb][2] = ex2(sf[nb][2] - m_hi);
            sf[nb][3] = ex2(sf[nb][3] - m_hi);
            rs_lo += sf[nb][0] + sf[nb][1];
            rs_hi += sf[nb][2] + sf[nb][3];
        }
        rs_lo += __shfl_xor_sync(0xffffffffu, rs_lo, 1);
        rs_lo += __shfl_xor_sync(0xffffffffu, rs_lo, 2);
        rs_hi += __shfl_xor_sync(0xffffffffu, rs_hi, 1);
        rs_hi += __shfl_xor_sync(0xffffffffu, rs_hi, 2);

        l_lo = l_lo * fac_lo + rs_lo;
        l_hi = l_hi * fac_hi + rs_hi;
#pragma unroll
        for (int nb = 0; nb < 8; nb++) {
            acc[nb][0] *= fac_lo; acc[nb][1] *= fac_lo;
            acc[nb][2] *= fac_hi; acc[nb][3] *= fac_hi;
        }

        // ---- acc += P V ----
        unsigned pa[4][4];
#pragma unroll
        for (int kc = 0; kc < 4; kc++) {
            pa[kc][0] = pack_h2(sf[2 * kc][0],     sf[2 * kc][1]);
            pa[kc][1] = pack_h2(sf[2 * kc][2],     sf[2 * kc][3]);
            pa[kc][2] = pack_h2(sf[2 * kc + 1][0], sf[2 * kc + 1][1]);
            pa[kc][3] = pack_h2(sf[2 * kc + 1][2], sf[2 * kc + 1][3]);
        }
#pragma unroll
        for (int nb = 0; nb < 8; nb++) {
            unsigned vv[8];
            uint32_t va = vst + ((nb * 8 + lm_row) * HST + lm_grp * 8) * 2;
            LDSM_X4(vv[0], vv[1], vv[2], vv[3], va);
            LDSM_X4(vv[4], vv[5], vv[6], vv[7], va + 64);
#pragma unroll
            for (int kc = 0; kc < 4; kc++)
                mma_f16(acc[nb], pa[kc][0], pa[kc][1], pa[kc][2], pa[kc][3],
                        vv[2 * kc], vv[2 * kc + 1]);
        }

        if (jt < 15) {
            __half* Kd = sm + ((jt + 1) & 1) * KTILE_H;
            __half* Vd = sm + 2 * KTILE_H + ((jt + 1) & 1) * KTILE_H;
            const int r  = t >> 3;
            const int c8 = (t & 7) * 8;
            *(uint4*)&Kd[r * HST + c8]        = rk[0];
            *(uint4*)&Kd[(r + 32) * HST + c8] = rk[1];
            *(uint4*)&Vd[r * HST + c8]        = rv[0];
            *(uint4*)&Vd[(r + 32) * HST + c8] = rv[1];
        }
        __syncthreads();
    }

    float inv_lo = 1.0f / l_lo;
    float inv_hi = 1.0f / l_hi;
    int tok_lo = sg * SEG + mt * 128 + warp * 16 + g;
#pragma unroll
    for (int nb = 0; nb < 8; nb++) {
        int col = h * DHEAD + nb * 8 + tg * 2;
        *(__half2*)&oh[(size_t)tok_lo * DMODEL + col] =
            __floats2half2_rn(acc[nb][0] * inv_lo, acc[nb][1] * inv_lo);
        *(__half2*)&oh[(size_t)(tok_lo + 8) * DMODEL + col] =
            __floats2half2_rn(acc[nb][2] * inv_hi, acc[nb][3] * inv_hi);
    }
}

// ---------------------------------------------------------------------------
// Launch
// ---------------------------------------------------------------------------
extern "C" void kernel_launch(void* const* d_in, const int* in_sizes, int n_in,
                              void* d_out, int out_size)
{
    const float* hs     = (const float*)d_in[0];
    const float* cosT   = (const float*)d_in[1];
    const float* sinT   = (const float*)d_in[2];
    const float* qkv_w  = (const float*)d_in[3];
    const float* qkv_b  = (const float*)d_in[4];
    const float* proj_w = (const float*)d_in[5];
    const float* proj_b = (const float*)d_in[6];
    float* out = (float*)d_out;

    void *qkh_v, *vt_v, *ah_v, *wh_v, *ph_v;
    cudaGetSymbolAddress(&qkh_v, g_qk_h);
    cudaGetSymbolAddress(&vt_v, g_vt);
    cudaGetSymbolAddress(&ah_v, g_ah);
    cudaGetSymbolAddress(&wh_v, g_wh);
    cudaGetSymbolAddress(&ph_v, g_ph);
    __half* qkh  = (__half*)qkh_v;
    __half* vtp  = (__half*)vt_v;
    __half* ahp  = (__half*)ah_v;
    __half* whp  = (__half*)wh_v;
    __half* php  = (__half*)ph_v;

    cudaFuncSetAttribute(gemm_qkv_fused,
                         cudaFuncAttributeMaxDynamicSharedMemorySize, GEMM_SMEM_B);
    cudaFuncSetAttribute(gemm_f16_out,
                         cudaFuncAttributeMaxDynamicSharedMemorySize, GEMM_SMEM_B);

    // 0) Converts
    conv_hi<<<(S_LEN * DMODEL / 4) / 256, 256>>>(hs, ahp, S_LEN * DMODEL / 4);
    conv_hi<<<(3 * DMODEL * DMODEL / 4) / 256, 256>>>(qkv_w, whp, 3 * DMODEL * DMODEL / 4);
    conv_hi<<<(DMODEL * DMODEL / 4) / 256, 256>>>(proj_w, php, DMODEL * DMODEL / 4);

    // 1) QKV GEMM with fused bias+RoPE+fp16 epilogue -> g_qk_h / g_vt
    {
        dim3 grid(3 * DMODEL / 128, S_LEN / 128);
        gemm_qkv_fused<<<grid, 256, GEMM_SMEM_B>>>(
            ahp, whp, qkv_b, cosT, sinT, qkh, vtp, S_LEN, 3 * DMODEL, DMODEL);
    }

    // 2) Attention -> fp16 proj input (g_ah reused)
    {
        dim3 grid(SEG / 128, NHEAD, NSEG);
        attn_f16_kernel<<<grid, 256>>>(qkh, vtp, ahp);
    }

    // 3) Output projection (plain fp16, 128x128 tiles)
    {
        dim3 grid(DMODEL / 128, S_LEN / 128);
        gemm_f16_out<<<grid, 256, GEMM_SMEM_B>>>(
            ahp, php, proj_b, out, S_LEN, DMODEL, DMODEL);
    }
}

// round 17
// speedup vs baseline: 1.1447x; 1.0318x over previous
#include <cuda_runtime.h>
#include <cuda_fp16.h>
#include <cstdint>
#include <math.h>

// Problem constants
#define S_LEN 8192
#define DMODEL 1024
#define NHEAD 16
#define DHEAD 64
#define NSEG 8
#define SEG 1024

// Scratch (device globals)
__device__ __half g_qk_h[S_LEN * 2 * DMODEL];        // [tok][ q | k ] roped fp16 (q log2-scaled)
__device__ __half g_vt[NSEG * NHEAD * DHEAD * SEG];  // [sg][h][d][tok] fp16
__device__ __half g_ah[S_LEN * DMODEL];              // hs fp16, then attn out fp16
__device__ __half g_wh[3 * DMODEL * DMODEL];
__device__ __half g_ph[DMODEL * DMODEL];

// ---------------------------------------------------------------------------
// helpers
// ---------------------------------------------------------------------------
__device__ __forceinline__ uint32_t smem_u32(const void* p) {
    uint32_t a;
    asm("{ .reg .u64 tmp; cvta.to.shared.u64 tmp, %1; cvt.u32.u64 %0, tmp; }"
        : "=r"(a) : "l"(p));
    return a;
}
__device__ __forceinline__ void cp16(uint32_t dst, const void* src) {
    asm volatile("cp.async.cg.shared.global [%0], [%1], 16;" :: "r"(dst), "l"(src));
}
#define CP_COMMIT() asm volatile("cp.async.commit_group;" ::: "memory")
#define CP_WAIT(n)  asm volatile("cp.async.wait_group %0;" :: "n"(n) : "memory")

#define LDSM_X4(r0, r1, r2, r3, addr)                                          \
    asm volatile("ldmatrix.sync.aligned.m8n8.x4.shared.b16 {%0,%1,%2,%3}, [%4];" \
        : "=r"(r0), "=r"(r1), "=r"(r2), "=r"(r3) : "r"(addr))

__device__ __forceinline__ void mma_f16(
    float c[4], unsigned a0, unsigned a1, unsigned a2, unsigned a3,
    unsigned b0, unsigned b1)
{
    asm volatile(
        "mma.sync.aligned.m16n8k16.row.col.f32.f16.f16.f32 "
        "{%0,%1,%2,%3},{%4,%5,%6,%7},{%8,%9},{%0,%1,%2,%3};"
        : "+f"(c[0]), "+f"(c[1]), "+f"(c[2]), "+f"(c[3])
        : "r"(a0), "r"(a1), "r"(a2), "r"(a3), "r"(b0), "r"(b1));
}
__device__ __forceinline__ unsigned pack_h2(float lo, float hi) {
    __half2 h = __floats2half2_rn(lo, hi);
    return *(unsigned*)&h;
}
__device__ __forceinline__ float ex2(float x) {
    float r;
    asm("ex2.approx.f32 %0, %1;" : "=f"(r) : "f"(x));
    return r;
}

// ---------------------------------------------------------------------------
// Merged fp32 -> fp16 converts (hs | qkv_w | proj_w) in one launch.
// ---------------------------------------------------------------------------
#define N4_HS  (S_LEN * DMODEL / 4)                 // 2,097,152
#define N4_QW  (3 * DMODEL * DMODEL / 4)            //   786,432
#define N4_PW  (DMODEL * DMODEL / 4)                //   262,144
#define N4_ALL (N4_HS + N4_QW + N4_PW)

__global__ void __launch_bounds__(256) conv_all(
    const float* __restrict__ hs, const float* __restrict__ qw,
    const float* __restrict__ pw,
    __half* __restrict__ ah, __half* __restrict__ wh, __half* __restrict__ ph)
{
    int i = blockIdx.x * 256 + threadIdx.x;
    const float* src;
    __half* dst;
    int j;
    if (i < N4_HS)              { src = hs; dst = ah; j = i; }
    else if (i < N4_HS + N4_QW) { src = qw; dst = wh; j = i - N4_HS; }
    else                        { src = pw; dst = ph; j = i - N4_HS - N4_QW; }
    float4 v = ((const float4*)src)[j];
    __half2* hp = (__half2*)(dst + 4 * (size_t)j);
    hp[0] = __floats2half2_rn(v.x, v.y);
    hp[1] = __floats2half2_rn(v.z, v.w);
}

// ---------------------------------------------------------------------------
// GEMM config: BM=128, BN=128, BK=64; 8 warps (4m x 2n), warp 32x64.
// 3-stage cp.async, single sync/iter, 2 CTAs/SM.
// ---------------------------------------------------------------------------
#define GST 72
#define STG_H 18432
#define BOFF 9216
#define NSTAGE 3
#define GEMM_SMEM_B (NSTAGE * STG_H * 2)   // 110592 bytes

#define GEMM_PROLOGUE_COMMON()                                                 \
    extern __shared__ __half sg[];                                             \
    const uint32_t sbase = smem_u32(sg);                                       \
    const int t      = threadIdx.x;                                            \
    const int lane   = t & 31;                                                 \
    const int warp   = t >> 5;                                                 \
    const int warp_m = warp >> 1;                                              \
    const int warp_n = warp & 1;                                               \
    const int g      = lane >> 2;                                              \
    const int tg     = lane & 3;                                               \
    const int m0 = blockIdx.y * 128;                                           \
    const int n0 = blockIdx.x * 128;

#define LOAD_STAGE_Q(stg, k0)                                                  \
    {                                                                          \
        uint32_t bb = sbase + (stg) * (STG_H * 2);                             \
        _Pragma("unroll")                                                      \
        for (int i = 0; i < 4; i++) {                                          \
            int id = t + i * 256;                                              \
            int r = id >> 3, c = (id & 7) * 8;                                 \
            cp16(bb + (r * GST + c) * 2, Ah + (size_t)(m0 + r) * K + (k0) + c);\
            cp16(bb + (BOFF + r * GST + c) * 2,                                \
                 Bh + (size_t)(n0 + r) * K + (k0) + c);                        \
        }                                                                      \
        CP_COMMIT();                                                           \
    }

#define GEMM_MAINLOOP()                                                        \
    float accm[2][8][4];                                                       \
    _Pragma("unroll")                                                          \
    for (int mi = 0; mi < 2; mi++)                                             \
        _Pragma("unroll")                                                      \
        for (int nb = 0; nb < 8; nb++)                                         \
            _Pragma("unroll")                                                  \
            for (int i = 0; i < 4; i++) accm[mi][nb][i] = 0.0f;                \
    const int nch = K >> 6;                                                    \
    LOAD_STAGE_Q(0, 0);                                                        \
    LOAD_STAGE_Q(1, 64);                                                       \
    const int a_row = warp_m * 32 + (lane & 15);                               \
    const int a_hc  = (lane >> 4) * 8;                                         \
    const int b_row = warp_n * 64 + ((lane >> 4) << 3) + (lane & 7);           \
    const int b_hc  = ((lane >> 3) & 1) * 8;                                   \
    for (int it = 0; it < nch; it++) {                                         \
        CP_WAIT(1);                                                            \
        __syncthreads();                                                       \
        if (it + 2 < nch) {                                                    \
            LOAD_STAGE_Q((it + 2) % NSTAGE, (it + 2) * 64);                    \
        } else {                                                               \
            CP_COMMIT();                                                       \
        }                                                                      \
        uint32_t bb = sbase + (it % NSTAGE) * (STG_H * 2);                     \
        _Pragma("unroll")                                                      \
        for (int ks = 0; ks < 4; ks++) {                                       \
            unsigned ah[2][4], bh[4][4];                                       \
            _Pragma("unroll")                                                  \
            for (int mi = 0; mi < 2; mi++) {                                   \
                uint32_t a = bb + ((a_row + mi * 16) * GST + ks * 16 + a_hc) * 2; \
                LDSM_X4(ah[mi][0], ah[mi][1], ah[mi][2], ah[mi][3], a);        \
            }                                                                  \
            _Pragma("unroll")                                                  \
            for (int p = 0; p < 4; p++) {                                      \
                uint32_t b = bb + (BOFF + (b_row + p * 16) * GST + ks * 16 + b_hc) * 2; \
                LDSM_X4(bh[p][0], bh[p][1], bh[p][2], bh[p][3], b);            \
            }                                                                  \
            _Pragma("unroll")                                                  \
            for (int p = 0; p < 4; p++)                                        \
                _Pragma("unroll")                                              \
                for (int q = 0; q < 2; q++) {                                  \
                    int nb = 2 * p + q;                                        \
                    _Pragma("unroll")                                          \
                    for (int mi = 0; mi < 2; mi++)                             \
                        mma_f16(accm[mi][nb], ah[mi][0], ah[mi][1], ah[mi][2], \
                                ah[mi][3], bh[p][2 * q], bh[p][2 * q + 1]);    \
                }                                                              \
        }                                                                      \
    }

// ---------------------------------------------------------------------------
// QKV GEMM fused: bias + RoPE epilogue (q scaled by 0.125*log2e), fp16 out.
// ---------------------------------------------------------------------------
__global__ void __launch_bounds__(256, 2) gemm_qkv_fused(
    const __half* __restrict__ Ah, const __half* __restrict__ Bh,
    const float* __restrict__ bias,
    const float* __restrict__ cosT, const float* __restrict__ sinT,
    __half* __restrict__ qk, __half* __restrict__ vt,
    int M, int N, int K)
{
    GEMM_PROLOGUE_COMMON();
    GEMM_MAINLOOP();

    const int sec = n0 >> 10;
    const int col_in_sec = (n0 & 1023) + warp_n * 64;

    if (sec < 2) {
        const float qs = (sec == 0) ? (0.125f * 1.44269504f) : 1.0f;
        const int outoff = sec * DMODEL + col_in_sec;
#pragma unroll
        for (int mi = 0; mi < 2; mi++) {
            int r0 = m0 + warp_m * 32 + mi * 16 + g;
#pragma unroll
            for (int nb = 0; nb < 4; nb++) {
                int d = nb * 8 + 2 * tg;
                int n_lo = n0 + warp_n * 64 + d;
                float bl0 = bias[n_lo],      bl1 = bias[n_lo + 1];
                float bh0 = bias[n_lo + 32], bh1 = bias[n_lo + 33];
#pragma unroll
                for (int hrow = 0; hrow < 2; hrow++) {
                    int row = r0 + hrow * 8;
                    float x0 = accm[mi][nb][2 * hrow + 0] + bl0;
                    float x1 = accm[mi][nb][2 * hrow + 1] + bl1;
                    float y0 = accm[mi][nb + 4][2 * hrow + 0] + bh0;
                    float y1 = accm[mi][nb + 4][2 * hrow + 1] + bh1;
                    float2 c1 = *(const float2*)&cosT[row * DHEAD + d];
                    float2 s1 = *(const float2*)&sinT[row * DHEAD + d];
                    float2 c2 = *(const float2*)&cosT[row * DHEAD + d + 32];
                    float2 s2 = *(const float2*)&sinT[row * DHEAD + d + 32];
                    __half2 lo = __floats2half2_rn((x0 * c1.x - y0 * s1.x) * qs,
                                                   (x1 * c1.y - y1 * s1.y) * qs);
                    __half2 hi = __floats2half2_rn((y0 * c2.x + x0 * s2.x) * qs,
                                                   (y1 * c2.y + x1 * s2.y) * qs);
                    __half* dst = qk + (size_t)row * (2 * DMODEL) + outoff + d;
                    *(__half2*)dst        = lo;
                    *(__half2*)(dst + 32) = hi;
                }
            }
        }
    } else {
        const int h  = col_in_sec >> 6;
        const int sgm = m0 >> 10;
        __half* vb = vt + ((size_t)(sgm * NHEAD + h) * DHEAD) * SEG;
#pragma unroll
        for (int mi = 0; mi < 2; mi++) {
            int r0 = m0 + warp_m * 32 + mi * 16 + g;
#pragma unroll
            for (int nb = 0; nb < 8; nb++) {
                int d = nb * 8 + 2 * tg;
                int n = n0 + warp_n * 64 + d;
                float b0 = bias[n], b1 = bias[n + 1];
#pragma unroll
                for (int hrow = 0; hrow < 2; hrow++) {
                    int row = r0 + hrow * 8;
                    int tin = row & 1023;
                    vb[(size_t)d * SEG + tin]       =
                        __float2half_rn(accm[mi][nb][2 * hrow + 0] + b0);
                    vb[(size_t)(d + 1) * SEG + tin] =
                        __float2half_rn(accm[mi][nb][2 * hrow + 1] + b1);
                }
            }
        }
    }
}

// ---------------------------------------------------------------------------
// Proj GEMM: plain fp16, 128x128 tiles, fp32 output + bias.
// ---------------------------------------------------------------------------
__global__ void __launch_bounds__(256, 2) gemm_f16_out(
    const __half* __restrict__ Ah, const __half* __restrict__ Bh,
    const float* __restrict__ bias, float* __restrict__ C,
    int M, int N, int K)
{
    GEMM_PROLOGUE_COMMON();
    GEMM_MAINLOOP();

#pragma unroll
    for (int mi = 0; mi < 2; mi++) {
        int row = m0 + warp_m * 32 + mi * 16 + g;
#pragma unroll
        for (int nb = 0; nb < 8; nb++) {
            int n = n0 + warp_n * 64 + nb * 8 + 2 * tg;
            float b0 = bias[n], b1 = bias[n + 1];
            float2 v;
            v.x = accm[mi][nb][0] + b0;
            v.y = accm[mi][nb][1] + b1;
            *(float2*)&C[(size_t)row * N + n] = v;
            v.x = accm[mi][nb][2] + b0;
            v.y = accm[mi][nb][3] + b1;
            *(float2*)&C[(size_t)(row + 8) * N + n] = v;
        }
    }
}

// ---------------------------------------------------------------------------
// fp16 flash attention; cp.async 3-stage K/V pipeline; log2-domain ex2.
// KV stage: K[64 keys][72] then V[64 dims][72] = 9216 halves (18432 B).
// ---------------------------------------------------------------------------
#define HST 72
#define KV_STG_H 9216
#define KOFF_V 4608

__global__ void __launch_bounds__(256, 2) attn_f16_kernel(
    const __half* __restrict__ qk, const __half* __restrict__ vt,
    __half* __restrict__ oh)
{
    __shared__ __half sm[3 * KV_STG_H];   // 55296 B; Q overlay uses stage 0 region
    __half* Qs = sm;

    const int mt = blockIdx.x;
    const int h  = blockIdx.y;
    const int sg = blockIdx.z;

    const int t    = threadIdx.x;
    const int lane = t & 31;
    const int warp = t >> 5;
    const int g    = lane >> 2;
    const int tg   = lane & 3;

    const int lm_row = lane & 7;
    const int lm_grp = lane >> 3;

    const uint32_t sbase = smem_u32(sm);
    const __half* kbase = qk + DMODEL + h * DHEAD;
    const __half* vbase = vt + (size_t)(sg * NHEAD + h) * DHEAD * SEG;

#define LOAD_KV(stg, j0)                                                       \
    {                                                                          \
        uint32_t bb = sbase + (stg) * (KV_STG_H * 2);                          \
        _Pragma("unroll")                                                      \
        for (int i = 0; i < 4; i++) {                                          \
            int id = t + i * 256;                                              \
            int r = (id >> 3) & 63;                                            \
            int c = (id & 7) * 8;                                              \
            if (id < 512)                                                      \
                cp16(bb + (r * HST + c) * 2,                                   \
                     kbase + (size_t)(sg * SEG + (j0) + r) * (2 * DMODEL) + c);\
            else                                                               \
                cp16(bb + (KOFF_V + r * HST + c) * 2,                          \
                     vbase + (size_t)r * SEG + (j0) + c);                      \
        }                                                                      \
        CP_COMMIT();                                                           \
    }

    // ---- Q tile: gmem -> smem (stage-0 overlay) ----
#pragma unroll
    for (int i = 0; i < 4; i++) {
        int f  = t + i * 256;
        int r  = f >> 3;
        int c8 = (f & 7) * 8;
        int tok = sg * SEG + mt * 128 + r;
        uint4 v = *(const uint4*)(qk + (size_t)tok * (2 * DMODEL) + h * DHEAD + c8);
        *(uint4*)&Qs[r * HST + c8] = v;
    }
    __syncthreads();

    unsigned qa[4][4];
    {
        int row = warp * 16 + g;
#pragma unroll
        for (int ks = 0; ks < 4; ks++) {
            int c = ks * 16 + 2 * tg;
            qa[ks][0] = *(const unsigned*)&Qs[row * HST + c];
            qa[ks][1] = *(const unsigned*)&Qs[(row + 8) * HST + c];
            qa[ks][2] = *(const unsigned*)&Qs[row * HST + c + 8];
            qa[ks][3] = *(const unsigned*)&Qs[(row + 8) * HST + c + 8];
        }
    }
    __syncthreads();

    LOAD_KV(0, 0);
    LOAD_KV(1, 64);

    float acc[8][4];
#pragma unroll
    for (int nb = 0; nb < 8; nb++)
#pragma unroll
        for (int i = 0; i < 4; i++) acc[nb][i] = 0.0f;
    float m_lo = -INFINITY, m_hi = -INFINITY, l_lo = 0.0f, l_hi = 0.0f;

    for (int jt = 0; jt < 16; jt++) {
        CP_WAIT(1);
        __syncthreads();
        if (jt + 2 < 16) {
            LOAD_KV((jt + 2) % 3, (jt + 2) * 64);
        } else {
            CP_COMMIT();
        }

        const uint32_t kst = sbase + (jt % 3) * (KV_STG_H * 2);
        const uint32_t vst = kst + KOFF_V * 2;

        // ---- S = Q K^T (log2 domain) ----
        float sf[8][4];
#pragma unroll
        for (int nb = 0; nb < 8; nb++) {
            sf[nb][0] = sf[nb][1] = sf[nb][2] = sf[nb][3] = 0.0f;
            unsigned kb[8];
            uint32_t ka = kst + ((nb * 8 + lm_row) * HST + lm_grp * 8) * 2;
            LDSM_X4(kb[0], kb[1], kb[2], kb[3], ka);
            LDSM_X4(kb[4], kb[5], kb[6], kb[7], ka + 64);
#pragma unroll
            for (int ks = 0; ks < 4; ks++)
                mma_f16(sf[nb], qa[ks][0], qa[ks][1], qa[ks][2], qa[ks][3],
                        kb[2 * ks], kb[2 * ks + 1]);
        }

        // ---- online softmax ----
        float tmax_lo = -INFINITY, tmax_hi = -INFINITY;
#pragma unroll
        for (int nb = 0; nb < 8; nb++) {
            tmax_lo = fmaxf(tmax_lo, fmaxf(sf[nb][0], sf[nb][1]));
            tmax_hi = fmaxf(tmax_hi, fmaxf(sf[nb][2], sf[nb][3]));
        }
        tmax_lo = fmaxf(tmax_lo, __shfl_xor_sync(0xffffffffu, tmax_lo, 1));
        tmax_lo = fmaxf(tmax_lo, __shfl_xor_sync(0xffffffffu, tmax_lo, 2));
        tmax_hi = fmaxf(tmax_hi, __shfl_xor_sync(0xffffffffu, tmax_hi, 1));
        tmax_hi = fmaxf(tmax_hi, __shfl_xor_sync(0xffffffffu, tmax_hi, 2));

        float mn_lo = fmaxf(m_lo, tmax_lo);
        float mn_hi = fmaxf(m_hi, tmax_hi);
        float fac_lo = ex2(m_lo - mn_lo);
        float fac_hi = ex2(m_hi - mn_hi);
        m_lo = mn_lo; m_hi = mn_hi;

        float rs_lo = 0.0f, rs_hi = 0.0f;
#pragma unroll
        for (int nb = 0; nb < 8; nb++) {
            sf[nb][0] = ex2(sf[nb][0] - m_lo);
            sf[nb][1] = ex2(sf[nb][1] - m_lo);
            sf[nb][2] = ex2(sf[nb][2] - m_hi);
            sf[nb][3] = ex2(sf[nb][3] - m_hi);
            rs_lo += sf[nb][0] + sf[nb][1];
            rs_hi += sf[nb][2] + sf[nb][3];
        }
        rs_lo += __shfl_xor_sync(0xffffffffu, rs_lo, 1);
        rs_lo += __shfl_xor_sync(0xffffffffu, rs_lo, 2);
        rs_hi += __shfl_xor_sync(0xffffffffu, rs_hi, 1);
        rs_hi += __shfl_xor_sync(0xffffffffu, rs_hi, 2);

        l_lo = l_lo * fac_lo + rs_lo;
        l_hi = l_hi * fac_hi + rs_hi;
#pragma unroll
        for (int nb = 0; nb < 8; nb++) {
            acc[nb][0] *= fac_lo; acc[nb][1] *= fac_lo;
            acc[nb][2] *= fac_hi; acc[nb][3] *= fac_hi;
        }

        // ---- acc += P V ----
        unsigned pa[4][4];
#pragma unroll
        for (int kc = 0; kc < 4; kc++) {
            pa[kc][0] = pack_h2(sf[2 * kc][0],     sf[2 * kc][1]);
            pa[kc][1] = pack_h2(sf[2 * kc][2],     sf[2 * kc][3]);
            pa[kc][2] = pack_h2(sf[2 * kc + 1][0], sf[2 * kc + 1][1]);
            pa[kc][3] = pack_h2(sf[2 * kc + 1][2], sf[2 * kc + 1][3]);
        }
#pragma unroll
        for (int nb = 0; nb < 8; nb++) {
            unsigned vv[8];
            uint32_t va = vst + ((nb * 8 + lm_row) * HST + lm_grp * 8) * 2;
            LDSM_X4(vv[0], vv[1], vv[2], vv[3], va);
            LDSM_X4(vv[4], vv[5], vv[6], vv[7], va + 64);
#pragma unroll
            for (int kc = 0; kc < 4; kc++)
                mma_f16(acc[nb], pa[kc][0], pa[kc][1], pa[kc][2], pa[kc][3],
                        vv[2 * kc], vv[2 * kc + 1]);
        }
    }

    float inv_lo = 1.0f / l_lo;
    float inv_hi = 1.0f / l_hi;
    int tok_lo = sg * SEG + mt * 128 + warp * 16 + g;
#pragma unroll
    for (int nb = 0; nb < 8; nb++) {
        int col = h * DHEAD + nb * 8 + tg * 2;
        *(__half2*)&oh[(size_t)tok_lo * DMODEL + col] =
            __floats2half2_rn(acc[nb][0] * inv_lo, acc[nb][1] * inv_lo);
        *(__half2*)&oh[(size_t)(tok_lo + 8) * DMODEL + col] =
            __floats2half2_rn(acc[nb][2] * inv_hi, acc[nb][3] * inv_hi);
    }
#undef LOAD_KV
}

// ---------------------------------------------------------------------------
// Launch
// ---------------------------------------------------------------------------
extern "C" void kernel_launch(void* const* d_in, const int* in_sizes, int n_in,
                              void* d_out, int out_size)
{
    const float* hs     = (const float*)d_in[0];
    const float* cosT   = (const float*)d_in[1];
    const float* sinT   = (const float*)d_in[2];
    const float* qkv_w  = (const float*)d_in[3];
    const float* qkv_b  = (const float*)d_in[4];
    const float* proj_w = (const float*)d_in[5];
    const float* proj_b = (const float*)d_in[6];
    float* out = (float*)d_out;

    void *qkh_v, *vt_v, *ah_v, *wh_v, *ph_v;
    cudaGetSymbolAddress(&qkh_v, g_qk_h);
    cudaGetSymbolAddress(&vt_v, g_vt);
    cudaGetSymbolAddress(&ah_v, g_ah);
    cudaGetSymbolAddress(&wh_v, g_wh);
    cudaGetSymbolAddress(&ph_v, g_ph);
    __half* qkh  = (__half*)qkh_v;
    __half* vtp  = (__half*)vt_v;
    __half* ahp  = (__half*)ah_v;
    __half* whp  = (__half*)wh_v;
    __half* php  = (__half*)ph_v;

    cudaFuncSetAttribute(gemm_qkv_fused,
                         cudaFuncAttributeMaxDynamicSharedMemorySize, GEMM_SMEM_B);
    cudaFuncSetAttribute(gemm_f16_out,
                         cudaFuncAttributeMaxDynamicSharedMemorySize, GEMM_SMEM_B);

    // 0) Converts (single launch)
    conv_all<<<N4_ALL / 256, 256>>>(hs, qkv_w, proj_w, ahp, whp, php);

    // 1) QKV GEMM with fused bias+RoPE+fp16 epilogue -> g_qk_h / g_vt
    {
        dim3 grid(3 * DMODEL / 128, S_LEN / 128);
        gemm_qkv_fused<<<grid, 256, GEMM_SMEM_B>>>(
            ahp, whp, qkv_b, cosT, sinT, qkh, vtp, S_LEN, 3 * DMODEL, DMODEL);
    }

    // 2) Attention -> fp16 proj input (g_ah reused)
    {
        dim3 grid(SEG / 128, NHEAD, NSEG);
        attn_f16_kernel<<<grid, 256>>>(qkh, vtp, ahp);
    }

    // 3) Output projection (plain fp16, 128x128 tiles)
    {
        dim3 grid(DMODEL / 128, S_LEN / 128);
        gemm_f16_out<<<grid, 256, GEMM_SMEM_B>>>(
            ahp, php, proj_b, out, S_LEN, DMODEL, DMODEL);
    }
}